// round 5
// baseline (speedup 1.0000x reference)
#include <cuda_runtime.h>
#include <cstdint>
#include <math.h>

#define NB 8
#define SS 2048
#define DM 1024
#define NH 16
#define DH 64
#define MROWS (NB * SS)
#define ELEMS ((size_t)MROWS * DM)

__device__ float g_At[ELEMS];            // k-permuted tf32-rounded A operand
__device__ float g_Q[ELEMS];             // Q = Q_seq @ WQ (fp32)
__device__ float g_QAK[ELEMS];           // QAK [b,h,s,dh]
__device__ float g_WT[DM * DM];          // transposed, k-permuted tf32 weight
__device__ float g_logits[NB * NH * SS];
__device__ float g_qglob[NB * DM];
__device__ float g_kglob[NB * DM];
__device__ float g_WaT[NH * DM];
__device__ float g_WbT[NH * DM];

// ---------------- helpers ----------------
__device__ __forceinline__ uint32_t smem_u32(const void* p) {
    uint32_t a;
    asm("{ .reg .u64 t; cvta.to.shared.u64 t, %1; cvt.u32.u64 %0, t; }" : "=r"(a) : "l"(p));
    return a;
}
__device__ __forceinline__ void cp_async16(uint32_t s, const void* g) {
    asm volatile("cp.async.cg.shared.global [%0], [%1], 16;" :: "r"(s), "l"(g));
}
__device__ __forceinline__ void cp_commit() { asm volatile("cp.async.commit_group;" ::: "memory"); }
template <int N> __device__ __forceinline__ void cp_wait() {
    asm volatile("cp.async.wait_group %0;" :: "n"(N) : "memory");
}
__device__ __forceinline__ float rna_tf32(float x) {
    float r;
    asm("cvt.rna.tf32.f32 %0, %1;" : "=f"(r) : "f"(x));
    return r;
}
__device__ __forceinline__ void mma_tf32(float* c, const uint32_t* a, const uint32_t* b) {
    asm volatile(
        "mma.sync.aligned.m16n8k8.row.col.f32.tf32.tf32.f32 "
        "{%0,%1,%2,%3}, {%4,%5,%6,%7}, {%8,%9}, {%0,%1,%2,%3};"
        : "+f"(c[0]), "+f"(c[1]), "+f"(c[2]), "+f"(c[3])
        : "r"(a[0]), "r"(a[1]), "r"(a[2]), "r"(a[3]), "r"(b[0]), "r"(b[1]));
}

// ---------------- mma.sync tf32 GEMM (k-permuted operands) ----------------
// C[M,N] = A[M,K] @ Bt[N,K]^T with A, Bt stored k-permuted:
// within each 32-k block, position j = (k%4)*8 + (k/4).
// BM=BN=128, BK=32, 256 threads, warp tile 32x64, 3-stage cp.async ring.
#define BKF 32
#define ASTR 36
#define TILE_F (128 * ASTR)
#define STAGE_F (2 * TILE_F)
#define NST 3
#define KITERS (DM / BKF)
#define DYN_SMEM (NST * STAGE_F * 4)

// MODE 0: plain store. MODE 1: scale by aux[b,n], scatter to [b,h,s,dh]. MODE 2: + aux residual.
template <int MODE>
__global__ __launch_bounds__(256, 2) void gemm_mma(
    const float* __restrict__ A, const float* __restrict__ Bt,
    float* __restrict__ C, const float* __restrict__ aux)
{
    extern __shared__ float sm[];
    const uint32_t sbase = smem_u32(sm);
    const int tid = threadIdx.x;
    const int wid = tid >> 5, lane = tid & 31;
    const int warpM = wid & 3, warpN = wid >> 2;      // 4 x 2 warp grid
    const int grp = lane >> 2, qid = lane & 3;
    const int rowM = blockIdx.y * 128, rowN = blockIdx.x * 128;

    float acc[2][8][4];
#pragma unroll
    for (int i = 0; i < 2; i++)
#pragma unroll
        for (int j = 0; j < 8; j++)
#pragma unroll
            for (int l = 0; l < 4; l++) acc[i][j][l] = 0.0f;

    auto prefetch = [&](int kt, int slot) {
        const uint32_t sA = sbase + (uint32_t)slot * STAGE_F * 4;
        const uint32_t sB = sA + TILE_F * 4;
        const int kbase = kt * BKF;
#pragma unroll
        for (int j = 0; j < 4; j++) {
            const int t = tid + j * 256;
            const int row = t >> 3, g = t & 7;
            cp_async16(sA + (uint32_t)(row * ASTR + g * 4) * 4,
                       A + (size_t)(rowM + row) * DM + kbase + g * 4);
        }
#pragma unroll
        for (int j = 0; j < 4; j++) {
            const int t = tid + j * 256;
            const int row = t >> 3, g = t & 7;
            cp_async16(sB + (uint32_t)(row * ASTR + g * 4) * 4,
                       Bt + (size_t)(rowN + row) * DM + kbase + g * 4);
        }
        cp_commit();
    };

    prefetch(0, 0);
    prefetch(1, 1);

    for (int kt = 0; kt < KITERS; kt++) {
        if (kt < KITERS - 1) cp_wait<1>(); else cp_wait<0>();
        __syncthreads();
        if (kt + 2 < KITERS) prefetch(kt + 2, (kt + 2) % NST);

        const float* As = sm + (kt % NST) * STAGE_F;
        const float* Bs = As + TILE_F;
        const int colb = qid * 8;      // this thread's 8-float fragment column base
#pragma unroll
        for (int h = 0; h < 2; h++) {  // ks = 2h, 2h+1
            float4 af[2][2];
#pragma unroll
            for (int mt = 0; mt < 2; mt++) {
                const int r = warpM * 32 + mt * 16 + grp;
                af[mt][0] = *(const float4*)&As[r * ASTR + colb + h * 4];
                af[mt][1] = *(const float4*)&As[(r + 8) * ASTR + colb + h * 4];
            }
#pragma unroll
            for (int nt = 0; nt < 8; nt++) {
                const int n = warpN * 64 + nt * 8 + grp;
                const float4 bf = *(const float4*)&Bs[n * ASTR + colb + h * 4];
                const float bfv[4] = {bf.x, bf.y, bf.z, bf.w};
#pragma unroll
                for (int s = 0; s < 2; s++) {
                    uint32_t b2[2] = {__float_as_uint(bfv[2 * s]),
                                      __float_as_uint(bfv[2 * s + 1])};
#pragma unroll
                    for (int mt = 0; mt < 2; mt++) {
                        const float* a0 = (const float*)&af[mt][0];
                        const float* a1 = (const float*)&af[mt][1];
                        uint32_t a4[4] = {__float_as_uint(a0[2 * s]),
                                          __float_as_uint(a1[2 * s]),
                                          __float_as_uint(a0[2 * s + 1]),
                                          __float_as_uint(a1[2 * s + 1])};
                        mma_tf32(acc[mt][nt], a4, b2);
                    }
                }
            }
        }
    }

    // Epilogue
    const int bB = rowM >> 11;
#pragma unroll
    for (int mt = 0; mt < 2; mt++) {
        const int r0 = rowM + warpM * 32 + mt * 16 + grp;
        const int r1 = r0 + 8;
        const int s0 = r0 & (SS - 1), s1 = r1 & (SS - 1);
#pragma unroll
        for (int nt = 0; nt < 8; nt++) {
            const int n = rowN + warpN * 64 + nt * 8 + qid * 2;
            const float* a4 = acc[mt][nt];
            if (MODE == 0) {
                *(float2*)(C + (size_t)r0 * DM + n) = make_float2(a4[0], a4[1]);
                *(float2*)(C + (size_t)r1 * DM + n) = make_float2(a4[2], a4[3]);
            } else if (MODE == 1) {
                const int h = n >> 6, d = n & 63;
                const float2 g = *(const float2*)(aux + (size_t)bB * DM + n);
                float* base = C + (((size_t)(bB * NH + h)) << 17) + d;
                *(float2*)(base + (size_t)s0 * DH) = make_float2(a4[0] * g.x, a4[1] * g.y);
                *(float2*)(base + (size_t)s1 * DH) = make_float2(a4[2] * g.x, a4[3] * g.y);
            } else {
                const float2 q0 = *(const float2*)(aux + (size_t)r0 * DM + n);
                const float2 q1 = *(const float2*)(aux + (size_t)r1 * DM + n);
                *(float2*)(C + (size_t)r0 * DM + n) = make_float2(a4[0] + q0.x, a4[1] + q0.y);
                *(float2*)(C + (size_t)r1 * DM + n) = make_float2(a4[2] + q1.x, a4[3] + q1.y);
            }
        }
    }
}

// ---------------- conversion / small kernels ----------------
// k-permuted store: within each 32-k block, j = (k%4)*8 + k/4.
// Thread handles float4 at k = 4m..4m+3 (same block) -> j = e*8 + (m&7).
__global__ __launch_bounds__(256) void conv_perm(
    const float4* __restrict__ in, float* __restrict__ out)
{
    const size_t i = (size_t)blockIdx.x * 256 + threadIdx.x;
    const float4 v = in[i];
    const size_t base = (i >> 3) << 5;   // 32-float block start
    const int m = (int)(i & 7);
    out[base + m]      = rna_tf32(v.x);
    out[base + 8 + m]  = rna_tf32(v.y);
    out[base + 16 + m] = rna_tf32(v.z);
    out[base + 24 + m] = rna_tf32(v.w);
}

__global__ __launch_bounds__(256) void conv_scale_perm(
    const float4* __restrict__ Q, const float* __restrict__ kg,
    float* __restrict__ out)
{
    const size_t i = (size_t)blockIdx.x * 256 + threadIdx.x;
    const int c4 = (int)(i & 255);
    const int b  = (int)(i >> 19);
    const float4 g = *(const float4*)(kg + (size_t)b * DM + c4 * 4);
    float4 v = Q[i];
    const size_t base = (i >> 3) << 5;
    const int m = (int)(i & 7);
    out[base + m]      = rna_tf32(v.x * g.x);
    out[base + 8 + m]  = rna_tf32(v.y * g.y);
    out[base + 16 + m] = rna_tf32(v.z * g.z);
    out[base + 24 + m] = rna_tf32(v.w * g.w);
}

__global__ void transpose_rna(const float* __restrict__ W, float* __restrict__ WT)
{
    __shared__ float t[32][33];
    const int x0 = blockIdx.x * 32, y0 = blockIdx.y * 32;
    const int tx = threadIdx.x, ty = threadIdx.y;  // 32 x 8
#pragma unroll
    for (int j = 0; j < 32; j += 8)
        t[ty + j][tx] = W[(size_t)(y0 + ty + j) * DM + x0 + tx];
    __syncthreads();
    // output col k = y0 + tx, permuted within its 32-block (y0 is 32-aligned)
    const int cp = y0 + ((tx & 3) << 3) + (tx >> 2);
#pragma unroll
    for (int j = 0; j < 32; j += 8)
        WT[(size_t)(x0 + ty + j) * DM + cp] = rna_tf32(t[tx][ty + j]);
}

__global__ void transpose_w(const float* __restrict__ W, float* __restrict__ WT)
{
    int i = blockIdx.x * 256 + threadIdx.x;
    if (i < DM * NH) {
        int j = i >> 4, e = i & 15;
        WT[e * DM + j] = W[i];
    }
}

__global__ __launch_bounds__(256) void row_logits(
    const float* __restrict__ rows, const float* __restrict__ WT,
    float* __restrict__ logits, float scaleF)
{
    const int r = blockIdx.x;
    __shared__ float4 srow[DM / 4];
    const int tid = threadIdx.x;
    srow[tid] = ((const float4*)(rows + (size_t)r * DM))[tid];
    __syncthreads();

    const int warp = tid >> 5, lane = tid & 31;
#pragma unroll
    for (int e = warp; e < NH; e += 8) {
        const float4* w4 = (const float4*)(WT + (size_t)e * DM);
        float4 a = make_float4(0.f, 0.f, 0.f, 0.f);
        for (int j = lane; j < DM / 4; j += 32) {
            const float4 sv = srow[j], wv = w4[j];
            a.x = fmaf(sv.x, wv.x, a.x); a.y = fmaf(sv.y, wv.y, a.y);
            a.z = fmaf(sv.z, wv.z, a.z); a.w = fmaf(sv.w, wv.w, a.w);
        }
        float p = (a.x + a.y) + (a.z + a.w);
#pragma unroll
        for (int o = 16; o; o >>= 1) p += __shfl_xor_sync(0xffffffffu, p, o);
        if (lane == 0) {
            const int b = r >> 11, s = r & (SS - 1);
            logits[((size_t)(b * NH + e)) * SS + s] = p * scaleF;
        }
    }
}

__global__ __launch_bounds__(256) void softmax_pool(
    const float* __restrict__ logits, const float* __restrict__ src,
    size_t bStride, size_t hStride, size_t sStride,
    float* __restrict__ out)
{
    const int bh = blockIdx.x;
    const int b = bh >> 4, h = bh & 15;
    const float* lg = logits + (size_t)bh * SS;

    __shared__ float w[SS];
    __shared__ float redm[8], reds[8];
    __shared__ float4 red4[16][16];
    __shared__ float s_max, s_inv;

    const int tid = threadIdx.x;
    const int warp = tid >> 5, lane = tid & 31;

    float m = -1e30f;
    for (int s = tid; s < SS; s += 256) m = fmaxf(m, lg[s]);
#pragma unroll
    for (int o = 16; o; o >>= 1) m = fmaxf(m, __shfl_xor_sync(0xffffffffu, m, o));
    if (lane == 0) redm[warp] = m;
    __syncthreads();
    if (tid == 0) {
        float mm = redm[0];
#pragma unroll
        for (int i = 1; i < 8; i++) mm = fmaxf(mm, redm[i]);
        s_max = mm;
    }
    __syncthreads();
    const float mx = s_max;

    float sum = 0.0f;
    for (int s = tid; s < SS; s += 256) {
        const float e = __expf(lg[s] - mx);
        w[s] = e;
        sum += e;
    }
#pragma unroll
    for (int o = 16; o; o >>= 1) sum += __shfl_xor_sync(0xffffffffu, sum, o);
    if (lane == 0) reds[warp] = sum;
    __syncthreads();
    if (tid == 0) {
        float ss = 0.0f;
#pragma unroll
        for (int i = 0; i < 8; i++) ss += reds[i];
        s_inv = 1.0f / ss;
    }
    __syncthreads();
    const float inv = s_inv;

    const int d4 = tid & 15, sg = tid >> 4;
    const float* sp = src + (size_t)b * bStride + (size_t)h * hStride + d4 * 4;
    float4 acc = make_float4(0.f, 0.f, 0.f, 0.f);
    for (int s = sg; s < SS; s += 16) {
        const float4 v = *(const float4*)(sp + (size_t)s * sStride);
        const float ws = w[s];
        acc.x = fmaf(ws, v.x, acc.x); acc.y = fmaf(ws, v.y, acc.y);
        acc.z = fmaf(ws, v.z, acc.z); acc.w = fmaf(ws, v.w, acc.w);
    }
    red4[sg][d4] = acc;
    __syncthreads();
    if (sg == 0) {
        float4 t = red4[0][d4];
#pragma unroll
        for (int g = 1; g < 16; g++) {
            const float4 u = red4[g][d4];
            t.x += u.x; t.y += u.y; t.z += u.z; t.w += u.w;
        }
        *(float4*)(out + (size_t)bh * DH + d4 * 4) =
            make_float4(t.x * inv, t.y * inv, t.z * inv, t.w * inv);
    }
}

// ---------------------------------------------------------------------------
extern "C" void kernel_launch(void* const* d_in, const int* in_sizes, int n_in,
                              void* d_out, int out_size)
{
    const float* Q_seq = (const float*)d_in[0];
    const float* K_seq = (const float*)d_in[1];
    const float* WQ = (const float*)d_in[3];
    const float* WK = (const float*)d_in[4];
    const float* Wa = (const float*)d_in[5];
    const float* Wb = (const float*)d_in[6];
    const float* WP = (const float*)d_in[7];
    float* out = (float*)d_out;

    float *pAt, *pQ, *pQAK, *pWT, *pLg, *pQg, *pKg, *pWaT, *pWbT;
    cudaGetSymbolAddress((void**)&pAt,  g_At);
    cudaGetSymbolAddress((void**)&pQ,   g_Q);
    cudaGetSymbolAddress((void**)&pQAK, g_QAK);
    cudaGetSymbolAddress((void**)&pWT,  g_WT);
    cudaGetSymbolAddress((void**)&pLg,  g_logits);
    cudaGetSymbolAddress((void**)&pQg,  g_qglob);
    cudaGetSymbolAddress((void**)&pKg,  g_kglob);
    cudaGetSymbolAddress((void**)&pWaT, g_WaT);
    cudaGetSymbolAddress((void**)&pWbT, g_WbT);

    cudaFuncSetAttribute(gemm_mma<0>, cudaFuncAttributeMaxDynamicSharedMemorySize, DYN_SMEM);
    cudaFuncSetAttribute(gemm_mma<1>, cudaFuncAttributeMaxDynamicSharedMemorySize, DYN_SMEM);
    cudaFuncSetAttribute(gemm_mma<2>, cudaFuncAttributeMaxDynamicSharedMemorySize, DYN_SMEM);

    const float scaleF = 0.125f;
    const dim3 ggrid(DM / 128, MROWS / 128);     // (8, 128)
    const dim3 tgrid(32, 32), tblk(32, 8);
    const unsigned cgrid = (unsigned)(ELEMS / 4 / 256);

    transpose_w<<<(DM * NH + 255) / 256, 256>>>(Wa, pWaT);
    transpose_w<<<(DM * NH + 255) / 256, 256>>>(Wb, pWbT);

    // 1. Q = Q_seq @ WQ (tf32 tensor)
    conv_perm<<<cgrid, 256>>>((const float4*)Q_seq, pAt);
    transpose_rna<<<tgrid, tblk>>>(WQ, pWT);
    gemm_mma<0><<<ggrid, 256, DYN_SMEM>>>(pAt, pWT, pQ, nullptr);

    // 2. alpha = softmax(Q @ Wa * scale); q_glob = pool(alpha, Qh)
    row_logits<<<MROWS, 256>>>(pQ, pWaT, pLg, scaleF);
    softmax_pool<<<NB * NH, 256>>>(pLg, pQ,
                                   (size_t)SS * DM, (size_t)DH, (size_t)DM, pQg);

    // 3. QAK = (K_seq @ WK) * q_glob, scattered to [b,h,s,dh]
    conv_perm<<<cgrid, 256>>>((const float4*)K_seq, pAt);
    transpose_rna<<<tgrid, tblk>>>(WK, pWT);
    gemm_mma<1><<<ggrid, 256, DYN_SMEM>>>(pAt, pWT, pQAK, pQg);

    // 4. beta = softmax(QAK_D @ Wb * scale); k_glob = pool(beta, QAK)
    row_logits<<<MROWS, 256>>>(pQAK, pWbT, pLg, scaleF);
    softmax_pool<<<NB * NH, 256>>>(pLg, pQAK,
                                   (size_t)NH * SS * DH, (size_t)SS * DH, (size_t)DH, pKg);

    // 5. out = (Q * k_glob) @ WP + Q
    conv_scale_perm<<<cgrid, 256>>>((const float4*)pQ, pKg, pAt);
    transpose_rna<<<tgrid, tblk>>>(WP, pWT);
    gemm_mma<2><<<ggrid, 256, DYN_SMEM>>>(pAt, pWT, out, pQ);
}

// round 6
// speedup vs baseline: 1.0038x; 1.0038x over previous
#include <cuda_runtime.h>
#include <cstdint>
#include <math.h>

#define NB 8
#define SS 2048
#define DM 1024
#define NH 16
#define DH 64
#define MROWS (NB * SS)
#define ELEMS ((size_t)MROWS * DM)

__device__ float g_At[ELEMS];            // tf32-rounded A operand (reused 3x)
__device__ float g_Q[ELEMS];             // Q = Q_seq @ WQ (fp32)
__device__ float g_QAK[ELEMS];           // QAK [b,h,s,dh]
__device__ float g_WT[DM * DM];          // transposed tf32 weight (reused 3x)
__device__ float g_logits[NB * NH * SS];
__device__ float g_qglob[NB * DM];
__device__ float g_kglob[NB * DM];
__device__ float g_WaT[NH * DM];
__device__ float g_WbT[NH * DM];

// ---------------- helpers ----------------
__device__ __forceinline__ uint32_t smem_u32(const void* p) {
    uint32_t a;
    asm("{ .reg .u64 t; cvta.to.shared.u64 t, %1; cvt.u32.u64 %0, t; }" : "=r"(a) : "l"(p));
    return a;
}
__device__ __forceinline__ void cp_async16(uint32_t s, const void* g) {
    asm volatile("cp.async.cg.shared.global [%0], [%1], 16;" :: "r"(s), "l"(g));
}
__device__ __forceinline__ void cp_commit() { asm volatile("cp.async.commit_group;" ::: "memory"); }
template <int N> __device__ __forceinline__ void cp_wait() {
    asm volatile("cp.async.wait_group %0;" :: "n"(N) : "memory");
}
__device__ __forceinline__ float rna_tf32(float x) {
    float r;
    asm("cvt.rna.tf32.f32 %0, %1;" : "=f"(r) : "f"(x));
    return r;
}
__device__ __forceinline__ void mma_tf32(float* c, const uint32_t* a, const uint32_t* b) {
    asm volatile(
        "mma.sync.aligned.m16n8k8.row.col.f32.tf32.tf32.f32 "
        "{%0,%1,%2,%3}, {%4,%5,%6,%7}, {%8,%9}, {%0,%1,%2,%3};"
        : "+f"(c[0]), "+f"(c[1]), "+f"(c[2]), "+f"(c[3])
        : "r"(a[0]), "r"(a[1]), "r"(a[2]), "r"(a[3]), "r"(b[0]), "r"(b[1]));
}

// ---------------- mma.sync tf32 GEMM (R4 version, verbatim) ----------------
// C[M,N] = A[M,K] @ Bt[N,K]^T ; M=16384, N=1024, K=1024.
// BM=BN=128, BK=32, 256 threads, warp tile 32x64, 3-stage cp.async ring.
#define BKF 32
#define ASTR 36                          // 32 + 4 pad floats
#define TILE_F (128 * ASTR)
#define STAGE_F (2 * TILE_F)
#define NST 3
#define KITERS (DM / BKF)
#define DYN_SMEM (NST * STAGE_F * 4)

// MODE 0: plain store. MODE 1: scale by aux[b,n], scatter to [b,h,s,dh]. MODE 2: + aux residual.
template <int MODE>
__global__ __launch_bounds__(256, 2) void gemm_mma(
    const float* __restrict__ A, const float* __restrict__ Bt,
    float* __restrict__ C, const float* __restrict__ aux)
{
    extern __shared__ float sm[];
    const uint32_t sbase = smem_u32(sm);
    const int tid = threadIdx.x;
    const int wid = tid >> 5, lane = tid & 31;
    const int warpM = wid & 3, warpN = wid >> 2;      // 4 x 2 warp grid
    const int grp = lane >> 2, qid = lane & 3;
    const int rowM = blockIdx.y * 128, rowN = blockIdx.x * 128;

    float acc[2][8][4];
#pragma unroll
    for (int i = 0; i < 2; i++)
#pragma unroll
        for (int j = 0; j < 8; j++)
#pragma unroll
            for (int l = 0; l < 4; l++) acc[i][j][l] = 0.0f;

    auto prefetch = [&](int kt, int slot) {
        const uint32_t sA = sbase + (uint32_t)slot * STAGE_F * 4;
        const uint32_t sB = sA + TILE_F * 4;
        const int kbase = kt * BKF;
#pragma unroll
        for (int j = 0; j < 4; j++) {
            const int t = tid + j * 256;
            const int row = t >> 3, g = t & 7;
            cp_async16(sA + (uint32_t)(row * ASTR + g * 4) * 4,
                       A + (size_t)(rowM + row) * DM + kbase + g * 4);
        }
#pragma unroll
        for (int j = 0; j < 4; j++) {
            const int t = tid + j * 256;
            const int row = t >> 3, g = t & 7;
            cp_async16(sB + (uint32_t)(row * ASTR + g * 4) * 4,
                       Bt + (size_t)(rowN + row) * DM + kbase + g * 4);
        }
        cp_commit();
    };

    prefetch(0, 0);
    prefetch(1, 1);

    for (int kt = 0; kt < KITERS; kt++) {
        if (kt < KITERS - 1) cp_wait<1>(); else cp_wait<0>();
        __syncthreads();
        if (kt + 2 < KITERS) prefetch(kt + 2, (kt + 2) % NST);

        const float* As = sm + (kt % NST) * STAGE_F;
        const float* Bs = As + TILE_F;
#pragma unroll
        for (int ks = 0; ks < 4; ks++) {
            const int c = ks * 8 + qid;
            uint32_t afr[2][4], bfr[8][2];
#pragma unroll
            for (int mt = 0; mt < 2; mt++) {
                const int r = warpM * 32 + mt * 16 + grp;
                afr[mt][0] = __float_as_uint(As[r * ASTR + c]);
                afr[mt][1] = __float_as_uint(As[(r + 8) * ASTR + c]);
                afr[mt][2] = __float_as_uint(As[r * ASTR + c + 4]);
                afr[mt][3] = __float_as_uint(As[(r + 8) * ASTR + c + 4]);
            }
#pragma unroll
            for (int nt = 0; nt < 8; nt++) {
                const int n = warpN * 64 + nt * 8 + grp;
                bfr[nt][0] = __float_as_uint(Bs[n * ASTR + c]);
                bfr[nt][1] = __float_as_uint(Bs[n * ASTR + c + 4]);
            }
#pragma unroll
            for (int mt = 0; mt < 2; mt++)
#pragma unroll
                for (int nt = 0; nt < 8; nt++)
                    mma_tf32(acc[mt][nt], afr[mt], bfr[nt]);
        }
    }

    // Epilogue
    const int bB = rowM >> 11;
#pragma unroll
    for (int mt = 0; mt < 2; mt++) {
        const int r0 = rowM + warpM * 32 + mt * 16 + grp;
        const int r1 = r0 + 8;
        const int s0 = r0 & (SS - 1), s1 = r1 & (SS - 1);
#pragma unroll
        for (int nt = 0; nt < 8; nt++) {
            const int n = rowN + warpN * 64 + nt * 8 + qid * 2;
            const float* a4 = acc[mt][nt];
            if (MODE == 0) {
                *(float2*)(C + (size_t)r0 * DM + n) = make_float2(a4[0], a4[1]);
                *(float2*)(C + (size_t)r1 * DM + n) = make_float2(a4[2], a4[3]);
            } else if (MODE == 1) {
                const int h = n >> 6, d = n & 63;
                const float2 g = *(const float2*)(aux + (size_t)bB * DM + n);
                float* base = C + (((size_t)(bB * NH + h)) << 17) + d;  // *2048*64
                *(float2*)(base + (size_t)s0 * DH) = make_float2(a4[0] * g.x, a4[1] * g.y);
                *(float2*)(base + (size_t)s1 * DH) = make_float2(a4[2] * g.x, a4[3] * g.y);
            } else {
                const float2 q0 = *(const float2*)(aux + (size_t)r0 * DM + n);
                const float2 q1 = *(const float2*)(aux + (size_t)r1 * DM + n);
                *(float2*)(C + (size_t)r0 * DM + n) = make_float2(a4[0] + q0.x, a4[1] + q0.y);
                *(float2*)(C + (size_t)r1 * DM + n) = make_float2(a4[2] + q1.x, a4[3] + q1.y);
            }
        }
    }
}

// ---------------- conversion / small kernels (R4 versions) ----------------
__global__ __launch_bounds__(256) void conv_rna(
    const float4* __restrict__ in, float4* __restrict__ out)
{
    const size_t i = (size_t)blockIdx.x * 256 + threadIdx.x;
    float4 v = in[i];
    v.x = rna_tf32(v.x); v.y = rna_tf32(v.y);
    v.z = rna_tf32(v.z); v.w = rna_tf32(v.w);
    out[i] = v;
}

__global__ __launch_bounds__(256) void conv_scale_rna(
    const float4* __restrict__ Q, const float* __restrict__ kg,
    float4* __restrict__ out)
{
    const size_t i = (size_t)blockIdx.x * 256 + threadIdx.x;
    const int c4 = (int)(i & 255);
    const int b  = (int)(i >> 19);
    const float4 g = *(const float4*)(kg + (size_t)b * DM + c4 * 4);
    float4 v = Q[i];
    v.x = rna_tf32(v.x * g.x); v.y = rna_tf32(v.y * g.y);
    v.z = rna_tf32(v.z * g.z); v.w = rna_tf32(v.w * g.w);
    out[i] = v;
}

__global__ void transpose_rna(const float* __restrict__ W, float* __restrict__ WT)
{
    __shared__ float t[32][33];
    const int x0 = blockIdx.x * 32, y0 = blockIdx.y * 32;
    const int tx = threadIdx.x, ty = threadIdx.y;  // 32 x 8
#pragma unroll
    for (int j = 0; j < 32; j += 8)
        t[ty + j][tx] = W[(size_t)(y0 + ty + j) * DM + x0 + tx];
    __syncthreads();
#pragma unroll
    for (int j = 0; j < 32; j += 8)
        WT[(size_t)(x0 + ty + j) * DM + y0 + tx] = rna_tf32(t[tx][ty + j]);
}

__global__ void transpose_w(const float* __restrict__ W, float* __restrict__ WT)
{
    int i = blockIdx.x * 256 + threadIdx.x;
    if (i < DM * NH) {
        int j = i >> 4, e = i & 15;
        WT[e * DM + j] = W[i];
    }
}

// ---------------- row_logits v2: weights in registers ----------------
// logits[b,e,s] = scaleF * dot(rows[r,:], WT[e,:]);  r = b*SS + s.
// 128 blocks x 128 rows. Warp w computes e = w and e = w+8.
// Lane l owns k-slice {j*128 + l*4 .. +3 | j=0..7} of both weight vectors
// (64 regs), loads the matching row slice with coalesced LDG.128.
__global__ __launch_bounds__(256) void row_logits16(
    const float* __restrict__ rows, const float* __restrict__ WT,
    float* __restrict__ logits, float scaleF)
{
    const int tid = threadIdx.x;
    const int wid = tid >> 5, lane = tid & 31;
    const int e0 = wid, e1 = wid + 8;

    float4 w0[8], w1[8];
#pragma unroll
    for (int j = 0; j < 8; j++) {
        w0[j] = *(const float4*)(WT + (size_t)e0 * DM + j * 128 + lane * 4);
        w1[j] = *(const float4*)(WT + (size_t)e1 * DM + j * 128 + lane * 4);
    }

    const int rbase = blockIdx.x * (MROWS / 128);
    for (int rr = 0; rr < MROWS / 128; rr++) {
        const int r = rbase + rr;
        const float* rp = rows + (size_t)r * DM + lane * 4;
        float a0 = 0.0f, a1 = 0.0f;
#pragma unroll
        for (int j = 0; j < 8; j++) {
            const float4 v = *(const float4*)(rp + j * 128);
            a0 = fmaf(v.x, w0[j].x, a0); a0 = fmaf(v.y, w0[j].y, a0);
            a0 = fmaf(v.z, w0[j].z, a0); a0 = fmaf(v.w, w0[j].w, a0);
            a1 = fmaf(v.x, w1[j].x, a1); a1 = fmaf(v.y, w1[j].y, a1);
            a1 = fmaf(v.z, w1[j].z, a1); a1 = fmaf(v.w, w1[j].w, a1);
        }
#pragma unroll
        for (int o = 16; o; o >>= 1) {
            a0 += __shfl_xor_sync(0xffffffffu, a0, o);
            a1 += __shfl_xor_sync(0xffffffffu, a1, o);
        }
        if (lane == 0) {
            const int b = r >> 11, s = r & (SS - 1);
            logits[((size_t)(b * NH + e0)) * SS + s] = a0 * scaleF;
            logits[((size_t)(b * NH + e1)) * SS + s] = a1 * scaleF;
        }
    }
}

__global__ __launch_bounds__(256) void softmax_pool(
    const float* __restrict__ logits, const float* __restrict__ src,
    size_t bStride, size_t hStride, size_t sStride,
    float* __restrict__ out)
{
    const int bh = blockIdx.x;
    const int b = bh >> 4, h = bh & 15;
    const float* lg = logits + (size_t)bh * SS;

    __shared__ float w[SS];
    __shared__ float redm[8], reds[8];
    __shared__ float4 red4[16][16];
    __shared__ float s_max, s_inv;

    const int tid = threadIdx.x;
    const int warp = tid >> 5, lane = tid & 31;

    float m = -1e30f;
    for (int s = tid; s < SS; s += 256) m = fmaxf(m, lg[s]);
#pragma unroll
    for (int o = 16; o; o >>= 1) m = fmaxf(m, __shfl_xor_sync(0xffffffffu, m, o));
    if (lane == 0) redm[warp] = m;
    __syncthreads();
    if (tid == 0) {
        float mm = redm[0];
#pragma unroll
        for (int i = 1; i < 8; i++) mm = fmaxf(mm, redm[i]);
        s_max = mm;
    }
    __syncthreads();
    const float mx = s_max;

    float sum = 0.0f;
    for (int s = tid; s < SS; s += 256) {
        const float e = __expf(lg[s] - mx);
        w[s] = e;
        sum += e;
    }
#pragma unroll
    for (int o = 16; o; o >>= 1) sum += __shfl_xor_sync(0xffffffffu, sum, o);
    if (lane == 0) reds[warp] = sum;
    __syncthreads();
    if (tid == 0) {
        float ss = 0.0f;
#pragma unroll
        for (int i = 0; i < 8; i++) ss += reds[i];
        s_inv = 1.0f / ss;
    }
    __syncthreads();
    const float inv = s_inv;

    const int d4 = tid & 15, sg = tid >> 4;
    const float* sp = src + (size_t)b * bStride + (size_t)h * hStride + d4 * 4;
    float4 acc = make_float4(0.f, 0.f, 0.f, 0.f);
    for (int s = sg; s < SS; s += 16) {
        const float4 v = *(const float4*)(sp + (size_t)s * sStride);
        const float ws = w[s];
        acc.x = fmaf(ws, v.x, acc.x); acc.y = fmaf(ws, v.y, acc.y);
        acc.z = fmaf(ws, v.z, acc.z); acc.w = fmaf(ws, v.w, acc.w);
    }
    red4[sg][d4] = acc;
    __syncthreads();
    if (sg == 0) {
        float4 t = red4[0][d4];
#pragma unroll
        for (int g = 1; g < 16; g++) {
            const float4 u = red4[g][d4];
            t.x += u.x; t.y += u.y; t.z += u.z; t.w += u.w;
        }
        *(float4*)(out + (size_t)bh * DH + d4 * 4) =
            make_float4(t.x * inv, t.y * inv, t.z * inv, t.w * inv);
    }
}

// ---------------------------------------------------------------------------
extern "C" void kernel_launch(void* const* d_in, const int* in_sizes, int n_in,
                              void* d_out, int out_size)
{
    const float* Q_seq = (const float*)d_in[0];
    const float* K_seq = (const float*)d_in[1];
    const float* WQ = (const float*)d_in[3];
    const float* WK = (const float*)d_in[4];
    const float* Wa = (const float*)d_in[5];
    const float* Wb = (const float*)d_in[6];
    const float* WP = (const float*)d_in[7];
    float* out = (float*)d_out;

    float *pAt, *pQ, *pQAK, *pWT, *pLg, *pQg, *pKg, *pWaT, *pWbT;
    cudaGetSymbolAddress((void**)&pAt,  g_At);
    cudaGetSymbolAddress((void**)&pQ,   g_Q);
    cudaGetSymbolAddress((void**)&pQAK, g_QAK);
    cudaGetSymbolAddress((void**)&pWT,  g_WT);
    cudaGetSymbolAddress((void**)&pLg,  g_logits);
    cudaGetSymbolAddress((void**)&pQg,  g_qglob);
    cudaGetSymbolAddress((void**)&pKg,  g_kglob);
    cudaGetSymbolAddress((void**)&pWaT, g_WaT);
    cudaGetSymbolAddress((void**)&pWbT, g_WbT);

    cudaFuncSetAttribute(gemm_mma<0>, cudaFuncAttributeMaxDynamicSharedMemorySize, DYN_SMEM);
    cudaFuncSetAttribute(gemm_mma<1>, cudaFuncAttributeMaxDynamicSharedMemorySize, DYN_SMEM);
    cudaFuncSetAttribute(gemm_mma<2>, cudaFuncAttributeMaxDynamicSharedMemorySize, DYN_SMEM);

    const float scaleF = 0.125f;
    const dim3 ggrid(DM / 128, MROWS / 128);     // (8, 128)
    const dim3 tgrid(32, 32), tblk(32, 8);
    const unsigned cgrid = (unsigned)(ELEMS / 4 / 256);

    transpose_w<<<(DM * NH + 255) / 256, 256>>>(Wa, pWaT);
    transpose_w<<<(DM * NH + 255) / 256, 256>>>(Wb, pWbT);

    // 1. Q = Q_seq @ WQ (tf32 tensor)
    conv_rna<<<cgrid, 256>>>((const float4*)Q_seq, (float4*)pAt);
    transpose_rna<<<tgrid, tblk>>>(WQ, pWT);
    gemm_mma<0><<<ggrid, 256, DYN_SMEM>>>(pAt, pWT, pQ, nullptr);

    // 2. alpha = softmax(Q @ Wa * scale); q_glob = pool(alpha, Qh)
    row_logits16<<<128, 256>>>(pQ, pWaT, pLg, scaleF);
    softmax_pool<<<NB * NH, 256>>>(pLg, pQ,
                                   (size_t)SS * DM, (size_t)DH, (size_t)DM, pQg);

    // 3. QAK = (K_seq @ WK) * q_glob, scattered to [b,h,s,dh]
    conv_rna<<<cgrid, 256>>>((const float4*)K_seq, (float4*)pAt);
    transpose_rna<<<tgrid, tblk>>>(WK, pWT);
    gemm_mma<1><<<ggrid, 256, DYN_SMEM>>>(pAt, pWT, pQAK, pQg);

    // 4. beta = softmax(QAK_D @ Wb * scale); k_glob = pool(beta, QAK)
    row_logits16<<<128, 256>>>(pQAK, pWbT, pLg, scaleF);
    softmax_pool<<<NB * NH, 256>>>(pLg, pQAK,
                                   (size_t)NH * SS * DH, (size_t)SS * DH, (size_t)DH, pKg);

    // 5. out = (Q * k_glob) @ WP + Q
    conv_scale_rna<<<cgrid, 256>>>((const float4*)pQ, pKg, (float4*)pAt);
    transpose_rna<<<tgrid, tblk>>>(WP, pWT);
    gemm_mma<2><<<ggrid, 256, DYN_SMEM>>>(pAt, pWT, out, pQ);
}

// round 8
// speedup vs baseline: 1.0735x; 1.0694x over previous
#include <cuda_runtime.h>
#include <cstdint>
#include <math.h>

#define NB 8
#define SS 2048
#define DM 1024
#define NH 16
#define DH 64
#define MROWS (NB * SS)
#define ELEMS ((size_t)MROWS * DM)

__device__ float g_At[ELEMS];            // tf32-rounded A operand (reused 3x)
__device__ float g_Q[ELEMS];             // Q = Q_seq @ WQ (fp32)
__device__ float g_QAK[ELEMS];           // QAK [b,h,s,dh]
__device__ float g_WT[DM * DM];          // transposed tf32 weight (reused 3x)
__device__ float g_logits[NB * NH * SS];
__device__ float g_qglob[NB * DM];
__device__ float g_kglob[NB * DM];
__device__ float g_WaT[NH * DM];
__device__ float g_WbT[NH * DM];

// ---------------- helpers ----------------
__device__ __forceinline__ uint32_t smem_u32(const void* p) {
    uint32_t a;
    asm("{ .reg .u64 t; cvta.to.shared.u64 t, %1; cvt.u32.u64 %0, t; }" : "=r"(a) : "l"(p));
    return a;
}
__device__ __forceinline__ void cp_async16(uint32_t s, const void* g) {
    asm volatile("cp.async.cg.shared.global [%0], [%1], 16;" :: "r"(s), "l"(g));
}
__device__ __forceinline__ void cp_commit() { asm volatile("cp.async.commit_group;" ::: "memory"); }
template <int N> __device__ __forceinline__ void cp_wait() {
    asm volatile("cp.async.wait_group %0;" :: "n"(N) : "memory");
}
__device__ __forceinline__ float rna_tf32(float x) {
    float r;
    asm("cvt.rna.tf32.f32 %0, %1;" : "=f"(r) : "f"(x));
    return r;
}
__device__ __forceinline__ void mma_tf32(float* c, const uint32_t* a, const uint32_t* b) {
    asm volatile(
        "mma.sync.aligned.m16n8k8.row.col.f32.tf32.tf32.f32 "
        "{%0,%1,%2,%3}, {%4,%5,%6,%7}, {%8,%9}, {%0,%1,%2,%3};"
        : "+f"(c[0]), "+f"(c[1]), "+f"(c[2]), "+f"(c[3])
        : "r"(a[0]), "r"(a[1]), "r"(a[2]), "r"(a[3]), "r"(b[0]), "r"(b[1]));
}

// ---------------- mma.sync tf32 GEMM (R4 version, verbatim) ----------------
#define BKF 32
#define ASTR 36
#define TILE_F (128 * ASTR)
#define STAGE_F (2 * TILE_F)
#define NST 3
#define KITERS (DM / BKF)
#define DYN_SMEM (NST * STAGE_F * 4)

// MODE 0: plain store. MODE 1: scale by aux[b,n], scatter to [b,h,s,dh]. MODE 2: + aux residual.
template <int MODE>
__global__ __launch_bounds__(256, 2) void gemm_mma(
    const float* __restrict__ A, const float* __restrict__ Bt,
    float* __restrict__ C, const float* __restrict__ aux)
{
    extern __shared__ float sm[];
    const uint32_t sbase = smem_u32(sm);
    const int tid = threadIdx.x;
    const int wid = tid >> 5, lane = tid & 31;
    const int warpM = wid & 3, warpN = wid >> 2;      // 4 x 2 warp grid
    const int grp = lane >> 2, qid = lane & 3;
    const int rowM = blockIdx.y * 128, rowN = blockIdx.x * 128;

    float acc[2][8][4];
#pragma unroll
    for (int i = 0; i < 2; i++)
#pragma unroll
        for (int j = 0; j < 8; j++)
#pragma unroll
            for (int l = 0; l < 4; l++) acc[i][j][l] = 0.0f;

    auto prefetch = [&](int kt, int slot) {
        const uint32_t sA = sbase + (uint32_t)slot * STAGE_F * 4;
        const uint32_t sB = sA + TILE_F * 4;
        const int kbase = kt * BKF;
#pragma unroll
        for (int j = 0; j < 4; j++) {
            const int t = tid + j * 256;
            const int row = t >> 3, g = t & 7;
            cp_async16(sA + (uint32_t)(row * ASTR + g * 4) * 4,
                       A + (size_t)(rowM + row) * DM + kbase + g * 4);
        }
#pragma unroll
        for (int j = 0; j < 4; j++) {
            const int t = tid + j * 256;
            const int row = t >> 3, g = t & 7;
            cp_async16(sB + (uint32_t)(row * ASTR + g * 4) * 4,
                       Bt + (size_t)(rowN + row) * DM + kbase + g * 4);
        }
        cp_commit();
    };

    prefetch(0, 0);
    prefetch(1, 1);

    for (int kt = 0; kt < KITERS; kt++) {
        if (kt < KITERS - 1) cp_wait<1>(); else cp_wait<0>();
        __syncthreads();
        if (kt + 2 < KITERS) prefetch(kt + 2, (kt + 2) % NST);

        const float* As = sm + (kt % NST) * STAGE_F;
        const float* Bs = As + TILE_F;
#pragma unroll
        for (int ks = 0; ks < 4; ks++) {
            const int c = ks * 8 + qid;
            uint32_t afr[2][4], bfr[8][2];
#pragma unroll
            for (int mt = 0; mt < 2; mt++) {
                const int r = warpM * 32 + mt * 16 + grp;
                afr[mt][0] = __float_as_uint(As[r * ASTR + c]);
                afr[mt][1] = __float_as_uint(As[(r + 8) * ASTR + c]);
                afr[mt][2] = __float_as_uint(As[r * ASTR + c + 4]);
                afr[mt][3] = __float_as_uint(As[(r + 8) * ASTR + c + 4]);
            }
#pragma unroll
            for (int nt = 0; nt < 8; nt++) {
                const int n = warpN * 64 + nt * 8 + grp;
                bfr[nt][0] = __float_as_uint(Bs[n * ASTR + c]);
                bfr[nt][1] = __float_as_uint(Bs[n * ASTR + c + 4]);
            }
#pragma unroll
            for (int mt = 0; mt < 2; mt++)
#pragma unroll
                for (int nt = 0; nt < 8; nt++)
                    mma_tf32(acc[mt][nt], afr[mt], bfr[nt]);
        }
    }

    // Epilogue
    const int bB = rowM >> 11;
#pragma unroll
    for (int mt = 0; mt < 2; mt++) {
        const int r0 = rowM + warpM * 32 + mt * 16 + grp;
        const int r1 = r0 + 8;
        const int s0 = r0 & (SS - 1), s1 = r1 & (SS - 1);
#pragma unroll
        for (int nt = 0; nt < 8; nt++) {
            const int n = rowN + warpN * 64 + nt * 8 + qid * 2;
            const float* a4 = acc[mt][nt];
            if (MODE == 0) {
                *(float2*)(C + (size_t)r0 * DM + n) = make_float2(a4[0], a4[1]);
                *(float2*)(C + (size_t)r1 * DM + n) = make_float2(a4[2], a4[3]);
            } else if (MODE == 1) {
                const int h = n >> 6, d = n & 63;
                const float2 g = *(const float2*)(aux + (size_t)bB * DM + n);
                float* base = C + (((size_t)(bB * NH + h)) << 17) + d;  // *2048*64
                *(float2*)(base + (size_t)s0 * DH) = make_float2(a4[0] * g.x, a4[1] * g.y);
                *(float2*)(base + (size_t)s1 * DH) = make_float2(a4[2] * g.x, a4[3] * g.y);
            } else {
                const float2 q0 = *(const float2*)(aux + (size_t)r0 * DM + n);
                const float2 q1 = *(const float2*)(aux + (size_t)r1 * DM + n);
                *(float2*)(C + (size_t)r0 * DM + n) = make_float2(a4[0] + q0.x, a4[1] + q0.y);
                *(float2*)(C + (size_t)r1 * DM + n) = make_float2(a4[2] + q1.x, a4[3] + q1.y);
            }
        }
    }
}

// ---------------- conversion / small kernels (R4 versions) ----------------
__global__ __launch_bounds__(256) void conv_rna(
    const float4* __restrict__ in, float4* __restrict__ out)
{
    const size_t i = (size_t)blockIdx.x * 256 + threadIdx.x;
    float4 v = in[i];
    v.x = rna_tf32(v.x); v.y = rna_tf32(v.y);
    v.z = rna_tf32(v.z); v.w = rna_tf32(v.w);
    out[i] = v;
}

__global__ __launch_bounds__(256) void conv_scale_rna(
    const float4* __restrict__ Q, const float* __restrict__ kg,
    float4* __restrict__ out)
{
    const size_t i = (size_t)blockIdx.x * 256 + threadIdx.x;
    const int c4 = (int)(i & 255);
    const int b  = (int)(i >> 19);
    const float4 g = *(const float4*)(kg + (size_t)b * DM + c4 * 4);
    float4 v = Q[i];
    v.x = rna_tf32(v.x * g.x); v.y = rna_tf32(v.y * g.y);
    v.z = rna_tf32(v.z * g.z); v.w = rna_tf32(v.w * g.w);
    out[i] = v;
}

__global__ void transpose_rna(const float* __restrict__ W, float* __restrict__ WT)
{
    __shared__ float t[32][33];
    const int x0 = blockIdx.x * 32, y0 = blockIdx.y * 32;
    const int tx = threadIdx.x, ty = threadIdx.y;  // 32 x 8
#pragma unroll
    for (int j = 0; j < 32; j += 8)
        t[ty + j][tx] = W[(size_t)(y0 + ty + j) * DM + x0 + tx];
    __syncthreads();
#pragma unroll
    for (int j = 0; j < 32; j += 8)
        WT[(size_t)(x0 + ty + j) * DM + y0 + tx] = rna_tf32(t[tx][ty + j]);
}

__global__ void transpose_w(const float* __restrict__ W, float* __restrict__ WT)
{
    int i = blockIdx.x * 256 + threadIdx.x;
    if (i < DM * NH) {
        int j = i >> 4, e = i & 15;
        WT[e * DM + j] = W[i];
    }
}

// ---------------- row_logits v3: smem weights + 1024 blocks ----------------
// logits[b,e,s] = scaleF * dot(rows[r,:], WT[e,:]);  r = b*SS + s.
// 1024 blocks x 16 rows. All 16 weight vectors staged in 64KB dynamic smem
// (one L2 read of 64KB per block = 64MB total, vs 1GB for block-per-row).
// Per row: warp w computes e=w and e=w+8; lane owns 8 float4 row slices.
#define LROWS 16
#define LOGIT_SMEM (NH * DM * 4)   // 65536
__global__ __launch_bounds__(256) void row_logits_sm(
    const float* __restrict__ rows, const float* __restrict__ WT,
    float* __restrict__ logits, float scaleF)
{
    extern __shared__ float4 w4[];   // [16 * 256] float4 = [e][256]
    const int tid = threadIdx.x;
    const int wid = tid >> 5, lane = tid & 31;

    const float4* wt4 = (const float4*)WT;
#pragma unroll
    for (int i = 0; i < NH; i++)
        w4[i * 256 + tid] = wt4[i * 256 + tid];
    __syncthreads();

    const float4* w0 = w4 + (size_t)wid * 256;
    const float4* w1 = w4 + (size_t)(wid + 8) * 256;
    const int rbase = blockIdx.x * LROWS;

    for (int rr = 0; rr < LROWS; rr++) {
        const int r = rbase + rr;
        const float4* rp = (const float4*)(rows + (size_t)r * DM);
        float4 v[8];
#pragma unroll
        for (int j = 0; j < 8; j++) v[j] = rp[j * 32 + lane];

        float a0 = 0.0f, a1 = 0.0f;
#pragma unroll
        for (int j = 0; j < 8; j++) {
            const float4 u0 = w0[j * 32 + lane];
            const float4 u1 = w1[j * 32 + lane];
            a0 = fmaf(v[j].x, u0.x, a0); a0 = fmaf(v[j].y, u0.y, a0);
            a0 = fmaf(v[j].z, u0.z, a0); a0 = fmaf(v[j].w, u0.w, a0);
            a1 = fmaf(v[j].x, u1.x, a1); a1 = fmaf(v[j].y, u1.y, a1);
            a1 = fmaf(v[j].z, u1.z, a1); a1 = fmaf(v[j].w, u1.w, a1);
        }
#pragma unroll
        for (int o = 16; o; o >>= 1) {
            a0 += __shfl_xor_sync(0xffffffffu, a0, o);
            a1 += __shfl_xor_sync(0xffffffffu, a1, o);
        }
        if (lane == 0) {
            const int b = r >> 11, s = r & (SS - 1);
            logits[((size_t)(b * NH + wid)) * SS + s]     = a0 * scaleF;
            logits[((size_t)(b * NH + wid + 8)) * SS + s] = a1 * scaleF;
        }
    }
}

__global__ __launch_bounds__(256) void softmax_pool(
    const float* __restrict__ logits, const float* __restrict__ src,
    size_t bStride, size_t hStride, size_t sStride,
    float* __restrict__ out)
{
    const int bh = blockIdx.x;
    const int b = bh >> 4, h = bh & 15;
    const float* lg = logits + (size_t)bh * SS;

    __shared__ float w[SS];
    __shared__ float redm[8], reds[8];
    __shared__ float4 red4[16][16];
    __shared__ float s_max, s_inv;

    const int tid = threadIdx.x;
    const int warp = tid >> 5, lane = tid & 31;

    float m = -1e30f;
    for (int s = tid; s < SS; s += 256) m = fmaxf(m, lg[s]);
#pragma unroll
    for (int o = 16; o; o >>= 1) m = fmaxf(m, __shfl_xor_sync(0xffffffffu, m, o));
    if (lane == 0) redm[warp] = m;
    __syncthreads();
    if (tid == 0) {
        float mm = redm[0];
#pragma unroll
        for (int i = 1; i < 8; i++) mm = fmaxf(mm, redm[i]);
        s_max = mm;
    }
    __syncthreads();
    const float mx = s_max;

    float sum = 0.0f;
    for (int s = tid; s < SS; s += 256) {
        const float e = __expf(lg[s] - mx);
        w[s] = e;
        sum += e;
    }
#pragma unroll
    for (int o = 16; o; o >>= 1) sum += __shfl_xor_sync(0xffffffffu, sum, o);
    if (lane == 0) reds[warp] = sum;
    __syncthreads();
    if (tid == 0) {
        float ss = 0.0f;
#pragma unroll
        for (int i = 0; i < 8; i++) ss += reds[i];
        s_inv = 1.0f / ss;
    }
    __syncthreads();
    const float inv = s_inv;

    const int d4 = tid & 15, sg = tid >> 4;
    const float* sp = src + (size_t)b * bStride + (size_t)h * hStride + d4 * 4;
    float4 acc = make_float4(0.f, 0.f, 0.f, 0.f);
    for (int s = sg; s < SS; s += 16) {
        const float4 v = *(const float4*)(sp + (size_t)s * sStride);
        const float ws = w[s];
        acc.x = fmaf(ws, v.x, acc.x); acc.y = fmaf(ws, v.y, acc.y);
        acc.z = fmaf(ws, v.z, acc.z); acc.w = fmaf(ws, v.w, acc.w);
    }
    red4[sg][d4] = acc;
    __syncthreads();
    if (sg == 0) {
        float4 t = red4[0][d4];
#pragma unroll
        for (int g = 1; g < 16; g++) {
            const float4 u = red4[g][d4];
            t.x += u.x; t.y += u.y; t.z += u.z; t.w += u.w;
        }
        *(float4*)(out + (size_t)bh * DH + d4 * 4) =
            make_float4(t.x * inv, t.y * inv, t.z * inv, t.w * inv);
    }
}

// ---------------------------------------------------------------------------
extern "C" void kernel_launch(void* const* d_in, const int* in_sizes, int n_in,
                              void* d_out, int out_size)
{
    const float* Q_seq = (const float*)d_in[0];
    const float* K_seq = (const float*)d_in[1];
    const float* WQ = (const float*)d_in[3];
    const float* WK = (const float*)d_in[4];
    const float* Wa = (const float*)d_in[5];
    const float* Wb = (const float*)d_in[6];
    const float* WP = (const float*)d_in[7];
    float* out = (float*)d_out;

    float *pAt, *pQ, *pQAK, *pWT, *pLg, *pQg, *pKg, *pWaT, *pWbT;
    cudaGetSymbolAddress((void**)&pAt,  g_At);
    cudaGetSymbolAddress((void**)&pQ,   g_Q);
    cudaGetSymbolAddress((void**)&pQAK, g_QAK);
    cudaGetSymbolAddress((void**)&pWT,  g_WT);
    cudaGetSymbolAddress((void**)&pLg,  g_logits);
    cudaGetSymbolAddress((void**)&pQg,  g_qglob);
    cudaGetSymbolAddress((void**)&pKg,  g_kglob);
    cudaGetSymbolAddress((void**)&pWaT, g_WaT);
    cudaGetSymbolAddress((void**)&pWbT, g_WbT);

    cudaFuncSetAttribute(gemm_mma<0>, cudaFuncAttributeMaxDynamicSharedMemorySize, DYN_SMEM);
    cudaFuncSetAttribute(gemm_mma<1>, cudaFuncAttributeMaxDynamicSharedMemorySize, DYN_SMEM);
    cudaFuncSetAttribute(gemm_mma<2>, cudaFuncAttributeMaxDynamicSharedMemorySize, DYN_SMEM);
    cudaFuncSetAttribute(row_logits_sm, cudaFuncAttributeMaxDynamicSharedMemorySize, LOGIT_SMEM);

    const float scaleF = 0.125f;
    const dim3 ggrid(DM / 128, MROWS / 128);     // (8, 128)
    const dim3 tgrid(32, 32), tblk(32, 8);
    const unsigned cgrid = (unsigned)(ELEMS / 4 / 256);

    transpose_w<<<(DM * NH + 255) / 256, 256>>>(Wa, pWaT);
    transpose_w<<<(DM * NH + 255) / 256, 256>>>(Wb, pWbT);

    // 1. Q = Q_seq @ WQ (tf32 tensor)
    conv_rna<<<cgrid, 256>>>((const float4*)Q_seq, (float4*)pAt);
    transpose_rna<<<tgrid, tblk>>>(WQ, pWT);
    gemm_mma<0><<<ggrid, 256, DYN_SMEM>>>(pAt, pWT, pQ, nullptr);

    // 2. alpha = softmax(Q @ Wa * scale); q_glob = pool(alpha, Qh)
    row_logits_sm<<<MROWS / LROWS, 256, LOGIT_SMEM>>>(pQ, pWaT, pLg, scaleF);
    softmax_pool<<<NB * NH, 256>>>(pLg, pQ,
                                   (size_t)SS * DM, (size_t)DH, (size_t)DM, pQg);

    // 3. QAK = (K_seq @ WK) * q_glob, scattered to [b,h,s,dh]
    conv_rna<<<cgrid, 256>>>((const float4*)K_seq, (float4*)pAt);
    transpose_rna<<<tgrid, tblk>>>(WK, pWT);
    gemm_mma<1><<<ggrid, 256, DYN_SMEM>>>(pAt, pWT, pQAK, pQg);

    // 4. beta = softmax(QAK_D @ Wb * scale); k_glob = pool(beta, QAK)
    row_logits_sm<<<MROWS / LROWS, 256, LOGIT_SMEM>>>(pQAK, pWbT, pLg, scaleF);
    softmax_pool<<<NB * NH, 256>>>(pLg, pQAK,
                                   (size_t)NH * SS * DH, (size_t)SS * DH, (size_t)DH, pKg);

    // 5. out = (Q * k_glob) @ WP + Q
    conv_scale_rna<<<cgrid, 256>>>((const float4*)pQ, pKg, (float4*)pAt);
    transpose_rna<<<tgrid, tblk>>>(WP, pWT);
    gemm_mma<2><<<ggrid, 256, DYN_SMEM>>>(pAt, pWT, out, pQ);
}